// round 6
// baseline (speedup 1.0000x reference)
#include <cuda_runtime.h>

// x: (64, 8, 32, 32) fp32. 1 center + 63 error rows, content = 8192 elements.
// Output = (1 + 63 + 8192) x 8192 = 270 MB.
#define N_CONTENT    8192
#define N_COL4       (N_CONTENT / 4)   // 2048
#define E_ROWS       64
#define NCHUNK       128               // 64 k's per chunk
#define ROWS_PER_BLK 4
#define TOTAL_ROWS   (E_ROWS + N_CONTENT)            // 8256
#define FILL_BLOCKS  (TOTAL_ROWS / ROWS_PER_BLK)     // 2064

// Scratch (__device__ globals; no allocation allowed)
__device__ float4   g_mult4[N_COL4];
__device__ float4   g_head4[N_COL4];
__device__ float    g_val[N_CONTENT];
__device__ unsigned g_mask[2 * NCHUNK];   // crossing-flag bitmask, 64 bits/chunk

// ---------------------------------------------------------------------------
// K1: prep — err reduction (4 threads per k), per-k scalars, flag bitmasks.
//     Triggers PDL immediately so the fill kernel's launch overlaps this work.
// ---------------------------------------------------------------------------
__global__ void prep_kernel(const float* __restrict__ x) {
    cudaTriggerProgrammaticLaunchCompletion();

    __shared__ float s_err[4][64];

    int t  = threadIdx.x;
    int kk = t & 63;
    int sl = t >> 6;                       // e-slice 0..3 (16 rows each)
    int k  = blockIdx.x * 64 + kk;

    int e0 = sl * 16 + (sl == 0 ? 1 : 0);  // skip center row
    int e1 = sl * 16 + 16;

    float p = 0.f;
#pragma unroll
    for (int e = e0; e < e1; e++)
        p += fabsf(x[e * N_CONTENT + k]);
    s_err[sl][kk] = p;
    __syncthreads();

    if (t < 64) {
        int kb = blockIdx.x * 64 + t;
        float err = s_err[0][t] + s_err[1][t] + s_err[2][t] + s_err[3][t];
        float c = x[kb];

        float upper = c + err;
        float lower = c - err;

        float cross  = (lower * upper < 0.f) ? 1.f : 0.f;
        float nonneg = (lower >= 0.f) ? 1.f : 0.f;

        // Reference-exact: lam = nonneg + cross*upper/(upper-lower), NaN -> 0.5
        float lam = nonneg + cross * (upper / (upper - lower));
        if (isnan(lam)) lam = 0.5f;

        float delta = fmaxf(-lam * lower, (1.f - lam) * upper);

        ((float*)g_mult4)[kb] = lam * cross + nonneg;
        ((float*)g_head4)[kb] = (delta * 0.5f + lam * c) * cross + c * nonneg;
        g_val[kb] = delta * 0.5f;

        int f = (cross > 0.f) ? 1 : 0;
        unsigned bal = __ballot_sync(0xffffffffu, f);
        if ((t & 31) == 0)
            g_mask[blockIdx.x * 2 + (t >> 5)] = bal;
    }
}

// ---------------------------------------------------------------------------
// K2: mega-fill — 4 rows per block (2064 blocks x 256). Launched with PDL;
//     waits on prep only at the point its blocks consume prep outputs.
// ---------------------------------------------------------------------------
__global__ void fill_kernel(const float4* __restrict__ x4, float4* __restrict__ out4) {
    int t  = threadIdx.x;
    int r0 = blockIdx.x * ROWS_PER_BLK;

    cudaGridDependencySynchronize();        // prep results visible from here

    if (r0 < E_ROWS) {                      // 16 blocks: head + body rows
#pragma unroll
        for (int j = 0; j < ROWS_PER_BLK; j++) {
            int r = r0 + j;
            float4* row = out4 + (long long)r * N_COL4;
            if (r == 0) {
#pragma unroll
                for (int jj = 0; jj < 8; jj++) {
                    int c4 = t + jj * 256;
                    row[c4] = g_head4[c4];
                }
            } else {
                const float4* xr = x4 + (long long)r * N_COL4;
#pragma unroll
                for (int jj = 0; jj < 8; jj++) {
                    int c4 = t + jj * 256;
                    float4 v = xr[c4];      // L2-hot
                    float4 m = g_mult4[c4];
                    v.x *= m.x; v.y *= m.y; v.z *= m.z; v.w *= m.w;
                    row[c4] = v;
                }
            }
        }
        return;
    }

    // ---- 4 tail rows: one chunk scan, then locate all 4 targets ----
    __shared__ int s_wtot[4];
    __shared__ int s_k[ROWS_PER_BLK];
    int lane = t & 31;
    int w = t >> 5;
    int tr0 = r0 - E_ROWS;                  // first tail row of this block

    if (t < ROWS_PER_BLK) s_k[t] = -1;

    unsigned m0 = 0, m1 = 0;
    int cnt = 0, incl = 0;
    if (t < NCHUNK) {                       // warps 0..3
        m0 = g_mask[2 * t];
        m1 = g_mask[2 * t + 1];
        cnt = __popc(m0) + __popc(m1);
        incl = cnt;
#pragma unroll
        for (int off = 1; off < 32; off <<= 1) {
            int n = __shfl_up_sync(0xffffffffu, incl, off);
            if (lane >= off) incl += n;
        }
        if (lane == 31) s_wtot[w] = incl;
    }
    __syncthreads();

    if (t < NCHUNK) {
        int wo = 0;
#pragma unroll
        for (int w2 = 0; w2 < 4; w2++)
            if (w2 < w) wo += s_wtot[w2];
        int excl = wo + incl - cnt;         // crossings before this chunk
        int p0 = __popc(m0);
#pragma unroll
        for (int j = 0; j < ROWS_PER_BLK; j++) {
            int tr = tr0 + j;
            if (tr >= excl && tr < excl + cnt) {
                int i = tr - excl;
                int pos = (i < p0) ? (int)__fns(m0, 0, i + 1)
                                   : 32 + (int)__fns(m1, 0, i - p0 + 1);
                s_k[j] = t * 64 + pos;
            }
        }
    }

    // stream zeros over the 4 rows
    float4 z = make_float4(0.f, 0.f, 0.f, 0.f);
    float4* base = out4 + (long long)r0 * N_COL4;
#pragma unroll
    for (int j = 0; j < ROWS_PER_BLK; j++) {
        float4* row = base + (long long)j * N_COL4;
#pragma unroll
        for (int jj = 0; jj < 8; jj++)
            __stcs(row + (t + jj * 256), z);
    }
    __syncthreads();                        // order patches after zeros

    if (t < ROWS_PER_BLK) {
        int k = s_k[t];
        if (k >= 0)
            ((float*)(base + (long long)t * N_COL4))[k] = g_val[k];
    }
}

// ---------------------------------------------------------------------------
extern "C" void kernel_launch(void* const* d_in, const int* in_sizes, int n_in,
                              void* d_out, int out_size) {
    const float* x = (const float*)d_in[0];
    float* out = (float*)d_out;

    prep_kernel<<<NCHUNK, 256>>>(x);

    // Fill launched with programmatic dependent launch: its launch/ramp
    // overlaps prep; blocks wait via cudaGridDependencySynchronize().
    cudaLaunchConfig_t cfg = {};
    cfg.gridDim  = dim3(FILL_BLOCKS, 1, 1);
    cfg.blockDim = dim3(256, 1, 1);
    cfg.dynamicSmemBytes = 0;
    cfg.stream = 0;
    cudaLaunchAttribute attr[1];
    attr[0].id = cudaLaunchAttributeProgrammaticStreamSerialization;
    attr[0].val.programmaticStreamSerializationAllowed = 1;
    cfg.attrs = attr;
    cfg.numAttrs = 1;
    cudaLaunchKernelEx(&cfg, fill_kernel, (const float4*)x, (float4*)out);
}

// round 7
// speedup vs baseline: 1.0529x; 1.0529x over previous
#include <cuda_runtime.h>

// x: (64, 8, 32, 32) fp32. 1 center + 63 error rows, content = 8192 elements.
// Output = (1 + 63 + 8192) x 8192 = 270 MB.
#define N_CONTENT 8192
#define N_COL4    (N_CONTENT / 4)   // 2048
#define E_ROWS    64
#define NCHUNK    128               // prep blocks; 64 k's per chunk

// Scratch (__device__ globals; no allocation allowed)
__device__ float4             g_mult4[N_COL4];
__device__ float4             g_head4[N_COL4];
__device__ int                g_col[N_CONTENT];    // tail row r -> column k
__device__ float              g_tval[N_CONTENT];   // tail row r -> delta/2
__device__ int                g_total;             // number of crossings
__device__ unsigned long long g_pub[NCHUNK];       // (epoch<<32)|count
__device__ unsigned           g_epoch[NCHUNK];     // per-block launch counter

// ---------------------------------------------------------------------------
// K1: prep — per-k scalars + replay-safe cross-block prefix -> inverse map.
//     128 blocks x 256 threads; each block owns 64 consecutive k's.
// ---------------------------------------------------------------------------
__global__ void prep_kernel(const float* __restrict__ x) {
    cudaTriggerProgrammaticLaunchCompletion();   // let fill_kernel start ramping

    __shared__ float    s_err[4][64];
    __shared__ unsigned s_mask[2];
    __shared__ unsigned s_ep;
    __shared__ int      s_excl;

    int t  = threadIdx.x;
    int b  = blockIdx.x;
    int kk = t & 63;
    int sl = t >> 6;                       // e-slice 0..3 (16 rows each)

    // partial |x| sums: 4 threads per k
    {
        int k  = b * 64 + kk;
        int e0 = sl * 16 + (sl == 0 ? 1 : 0);   // skip center row
        int e1 = sl * 16 + 16;
        float p = 0.f;
#pragma unroll
        for (int e = e0; e < e1; e++)
            p += fabsf(x[e * N_CONTENT + k]);
        s_err[sl][kk] = p;
    }
    __syncthreads();

    int   flag = 0;
    float val  = 0.f;
    if (t < 64) {                          // warps 0,1 fully active
        int k = b * 64 + t;
        float err = s_err[0][t] + s_err[1][t] + s_err[2][t] + s_err[3][t];
        float c = x[k];

        float upper = c + err;
        float lower = c - err;

        float cross  = (lower * upper < 0.f) ? 1.f : 0.f;
        float nonneg = (lower >= 0.f) ? 1.f : 0.f;

        // Reference-exact: lam = nonneg + cross*upper/(upper-lower), NaN -> 0.5
        float lam = nonneg + cross * (upper / (upper - lower));
        if (isnan(lam)) lam = 0.5f;

        float delta = fmaxf(-lam * lower, (1.f - lam) * upper);

        ((float*)g_mult4)[k] = lam * cross + nonneg;
        ((float*)g_head4)[k] = (delta * 0.5f + lam * c) * cross + c * nonneg;

        flag = (cross > 0.f) ? 1 : 0;
        val  = delta * 0.5f;

        unsigned bal = __ballot_sync(0xffffffffu, flag);
        if ((t & 31) == 0) s_mask[t >> 5] = bal;
    }
    __syncthreads();

    int cnt = __popc(s_mask[0]) + __popc(s_mask[1]);

    // publish (epoch, count): epochs advance once per block per launch, so
    // readers match on epoch and never see a previous launch's word.
    if (t == 0) {
        unsigned e = g_epoch[b] + 1;
        g_epoch[b] = e;
        atomicExch(&g_pub[b], ((unsigned long long)e << 32) | (unsigned)cnt);
        s_ep = e;
    }
    __syncthreads();
    unsigned myep = s_ep;

    // warp 0: sum all predecessor counts (32-wide, MLP-overlapped polling)
    if (t < 32) {
        int sum = 0;
        for (int i = t; i < b; i += 32) {
            unsigned long long w2;
            do {
                w2 = *((volatile unsigned long long*)&g_pub[i]);
            } while ((unsigned)(w2 >> 32) != myep);
            sum += (int)(w2 & 0xffffffffu);
        }
#pragma unroll
        for (int off = 16; off > 0; off >>= 1)
            sum += __shfl_down_sync(0xffffffffu, sum, off);
        if (t == 0) s_excl = sum;
    }
    __syncthreads();
    int excl = s_excl;

    if (t < 64 && flag) {
        unsigned m0 = s_mask[0], m1 = s_mask[1];
        int rank = (t < 32) ? __popc(m0 & ((1u << t) - 1u))
                            : __popc(m0) + __popc(m1 & ((1u << (t - 32)) - 1u));
        int r = excl + rank;
        r = min(r, N_CONTENT - 1);          // matches jnp.clip
        g_col[r]  = b * 64 + t;
        g_tval[r] = val;
    }
    if (b == NCHUNK - 1 && t == 0)
        g_total = excl + cnt;
}

// ---------------------------------------------------------------------------
// K2: mega-fill — one row per block (8256 x 256), minimal registers.
//     Tail rows: stream zeros + single patch from the prep-built inverse map.
// ---------------------------------------------------------------------------
__global__ void fill_kernel(const float4* __restrict__ x4, float4* __restrict__ out4) {
    int r = blockIdx.x;
    int t = threadIdx.x;

    cudaGridDependencySynchronize();        // prep results visible from here

    float4* row = out4 + (long long)r * N_COL4;

    if (r == 0) {
#pragma unroll
        for (int j = 0; j < 8; j++) {
            int c4 = t + j * 256;
            row[c4] = g_head4[c4];
        }
        return;
    }
    if (r < E_ROWS) {
        const float4* xr = x4 + (long long)r * N_COL4;
#pragma unroll
        for (int j = 0; j < 8; j++) {
            int c4 = t + j * 256;
            float4 v = xr[c4];              // L2-hot
            float4 m = g_mult4[c4];
            v.x *= m.x; v.y *= m.y; v.z *= m.z; v.w *= m.w;
            row[c4] = v;
        }
        return;
    }

    // tail row
    int tr = r - E_ROWS;
    int   k = -1;
    float v = 0.f;
    if (t == 0 && tr < g_total) {           // loads overlap the stores below
        k = g_col[tr];
        v = g_tval[tr];
    }

    float4 z = make_float4(0.f, 0.f, 0.f, 0.f);
#pragma unroll
    for (int j = 0; j < 8; j++)
        __stcs(row + (t + j * 256), z);
    __syncthreads();                        // order patch after zeros

    if (k >= 0)
        ((float*)row)[k] = v;
}

// ---------------------------------------------------------------------------
extern "C" void kernel_launch(void* const* d_in, const int* in_sizes, int n_in,
                              void* d_out, int out_size) {
    const float* x = (const float*)d_in[0];
    float* out = (float*)d_out;

    prep_kernel<<<NCHUNK, 256>>>(x);

    // PDL: fill's launch/ramp overlaps prep; blocks gate on grid dependency.
    cudaLaunchConfig_t cfg = {};
    cfg.gridDim  = dim3(E_ROWS + N_CONTENT, 1, 1);   // 8256
    cfg.blockDim = dim3(256, 1, 1);
    cfg.dynamicSmemBytes = 0;
    cfg.stream = 0;
    cudaLaunchAttribute attr[1];
    attr[0].id = cudaLaunchAttributeProgrammaticStreamSerialization;
    attr[0].val.programmaticStreamSerializationAllowed = 1;
    cfg.attrs = attr;
    cfg.numAttrs = 1;
    cudaLaunchKernelEx(&cfg, fill_kernel, (const float4*)x, (float4*)out);
}